// round 1
// baseline (speedup 1.0000x reference)
#include <cuda_runtime.h>
#include <math.h>

// Problem constants
#define BB 16
#define CC 12
#define CONDC 4
#define HH 128
#define WW 128
#define HID 64
#define STEP 23
#define HW (HH*WW)            // 16384
#define XOUT_SIZE (BB*CC*HW)  // 3145728

// Scratch (device globals — no cudaMalloc allowed)
__device__ float g_h1[BB*HID*HW];      // 64 MB
__device__ float g_h2[BB*HID*HW];      // 64 MB
__device__ float g_W1t[144*HID];       // [k=ic*9+kh*3+kw][oc]
__device__ float g_W2t[HID*HID];       // [ic][oc]
__device__ float g_W3t[CC*576*24];     // [c][k][s padded to 24]
__device__ float g_lad[BB*32];         // per-(image, tile) logdet partials

// ---------------------------------------------------------------------------
// Weight transposes: make every smem weight stage a linear float4 copy.
// ---------------------------------------------------------------------------
__global__ void k_trans(const float* __restrict__ W1,
                        const float* __restrict__ W2,
                        const float* __restrict__ W3) {
    int i = blockIdx.x * 256 + threadIdx.x;
    if (i < 144*64) {
        int k = i >> 6, oc = i & 63;
        g_W1t[i] = W1[oc*144 + k];
    }
    int j = i - 144*64;
    if (j >= 0 && j < 64*64) {
        int ic = j >> 6, oc = j & 63;
        g_W2t[j] = W2[oc*64 + ic];
    }
    int m = j - 64*64;
    if (m >= 0 && m < CC*576*24) {
        int c = m / 13824; int r = m - c*13824;
        int k = r / 24;    int s = r - k*24;
        g_W3t[m] = (s < 23) ? W3[(c*23 + s)*576 + k] : 0.f;
    }
}

// ---------------------------------------------------------------------------
// conv1 (16 -> 64, 3x3, pad 1) + ReLU.  Input z = [mask*x (12ch), cond (4ch)]
// built on the fly.  16x32 pixel tile per block, 2 px/thread, 2 oc halves.
// ---------------------------------------------------------------------------
__global__ void __launch_bounds__(256) k_conv1(const float* __restrict__ x,
                                               const float* __restrict__ cond,
                                               const float* __restrict__ b1) {
    extern __shared__ float sm[];
    float* sIn = sm;          // 16 * 612 (18x34 halo tile)
    float* sW  = sm + 9792;   // 144 * 64

    int b = blockIdx.y;
    int tile = blockIdx.x;
    int r0 = (tile >> 2) << 4;
    int c0 = (tile & 3) << 5;
    int t = threadIdx.x;

    // stage weights (linear copy)
    {
        const float4* src = (const float4*)g_W1t;
        float4* dst = (float4*)sW;
        for (int i = t; i < 9216/4; i += 256) dst[i] = src[i];
    }
    // stage input tile with halo; masked x for ch<12, conditioning for ch>=12
    for (int i = t; i < 16*612; i += 256) {
        int ch = i / 612; int rem = i - ch*612;
        int lr = rem / 34; int lc = rem - lr*34;
        int gr = r0 + lr - 1, gc = c0 + lc - 1;
        float v = 0.f;
        if ((unsigned)gr < 128u && (unsigned)gc < 128u) {
            if (ch < 12)
                v = ((gr + gc) & 1) ? x[(((b*12 + ch) << 7) + gr)*128 + gc] : 0.f;
            else
                v = cond[(((b*4 + (ch-12)) << 7) + gr)*128 + gc];
        }
        sIn[i] = v;
    }
    __syncthreads();

    int r = t >> 4, cx = (t & 15) << 1;
    int gr = r0 + r, gc = c0 + cx;

    #pragma unroll
    for (int half = 0; half < 2; half++) {
        float a0[32], a1[32];
        #pragma unroll
        for (int s = 0; s < 32; s++) { float bb = b1[half*32 + s]; a0[s] = bb; a1[s] = bb; }
        for (int ic = 0; ic < 16; ic++) {
            #pragma unroll
            for (int kh = 0; kh < 3; kh++) {
                const float* inr = &sIn[ic*612 + (r + kh)*34 + cx];
                #pragma unroll
                for (int kw = 0; kw < 3; kw++) {
                    float v0 = inr[kw];
                    float v1 = inr[kw + 1];
                    const float4* wr = (const float4*)&sW[((ic*3 + kh)*3 + kw)*64 + half*32];
                    #pragma unroll
                    for (int q = 0; q < 8; q++) {
                        float4 w = wr[q];
                        a0[q*4+0] = fmaf(w.x, v0, a0[q*4+0]); a1[q*4+0] = fmaf(w.x, v1, a1[q*4+0]);
                        a0[q*4+1] = fmaf(w.y, v0, a0[q*4+1]); a1[q*4+1] = fmaf(w.y, v1, a1[q*4+1]);
                        a0[q*4+2] = fmaf(w.z, v0, a0[q*4+2]); a1[q*4+2] = fmaf(w.z, v1, a1[q*4+2]);
                        a0[q*4+3] = fmaf(w.w, v0, a0[q*4+3]); a1[q*4+3] = fmaf(w.w, v1, a1[q*4+3]);
                    }
                }
            }
        }
        #pragma unroll
        for (int s = 0; s < 32; s++) {
            int oc = half*32 + s;
            float2 o; o.x = fmaxf(a0[s], 0.f); o.y = fmaxf(a1[s], 0.f);
            *(float2*)&g_h1[(((b*64 + oc) << 7) + gr)*128 + gc] = o;
        }
    }
}

// ---------------------------------------------------------------------------
// conv2 (64 -> 64, 1x1) + ReLU.  One pixel per thread, 64 accumulators.
// ---------------------------------------------------------------------------
__global__ void __launch_bounds__(256) k_conv2(const float* __restrict__ b2) {
    __shared__ float sW[64*64];
    __shared__ float sB[64];
    int t = threadIdx.x;
    for (int i = t; i < 4096/4; i += 256) ((float4*)sW)[i] = ((const float4*)g_W2t)[i];
    if (t < 64) sB[t] = b2[t];
    __syncthreads();

    int pix = blockIdx.x * 256 + t;
    int b = pix >> 14; int p = pix & 16383;
    const float* in = g_h1 + ((size_t)b << 20) + p;

    float acc[64];
    #pragma unroll
    for (int oc = 0; oc < 64; oc++) acc[oc] = sB[oc];

    #pragma unroll 4
    for (int ic = 0; ic < 64; ic++) {
        float v = in[ic << 14];
        const float4* wr = (const float4*)&sW[ic*64];
        #pragma unroll
        for (int q = 0; q < 16; q++) {
            float4 w = wr[q];
            acc[q*4+0] = fmaf(w.x, v, acc[q*4+0]);
            acc[q*4+1] = fmaf(w.y, v, acc[q*4+1]);
            acc[q*4+2] = fmaf(w.z, v, acc[q*4+2]);
            acc[q*4+3] = fmaf(w.w, v, acc[q*4+3]);
        }
    }
    float* outp = g_h2 + ((size_t)b << 20) + p;
    #pragma unroll
    for (int oc = 0; oc < 64; oc++) outp[oc << 14] = fmaxf(acc[oc], 0.f);
}

// ---------------------------------------------------------------------------
// Rational-quadratic spline, 8 bins, tails linear outside [-3, 3].
// p[0..7]=uw, p[8..15]=uh, p[16..22]=ud.  Register-resident scan selects the
// bin without dynamic indexing (no local-memory spills).
// ---------------------------------------------------------------------------
__device__ __forceinline__ float rqs_eval(const float* p, float xa, float& lad) {
    bool inside = (xa >= -3.f) && (xa <= 3.f);
    float xc = fminf(fmaxf(xa, -3.f), 3.f);

    float mw = p[0], mh = p[8];
    #pragma unroll
    for (int k = 1; k < 8; k++) { mw = fmaxf(mw, p[k]); mh = fmaxf(mh, p[8+k]); }
    float ew[8], eh[8]; float sw = 0.f, sh = 0.f;
    #pragma unroll
    for (int k = 0; k < 8; k++) {
        ew[k] = expf(p[k] - mw);   sw += ew[k];
        eh[k] = expf(p[8+k] - mh); sh += eh[k];
    }
    float rw = (1.f - 0.008f) / sw;   // (1 - MBW*K)/sum
    float rh = (1.f - 0.008f) / sh;

    float sp[7];
    #pragma unroll
    for (int k = 0; k < 7; k++) {
        float u = p[16 + k];
        sp[k] = (u > 15.f) ? u : log1pf(expf(u));
    }

    // scan knots; select bin = largest k in [0,7] with xc >= cw[k]
    float cw = -3.f, ch = -3.f, cumw = 0.f, cumh = 0.f, dprev = 1.f;
    float icw = -3.f, iw = 1.f, ich = -3.f, ih = 1.f, id0 = 1.f, id1 = 1.f;
    #pragma unroll
    for (int k = 0; k < 8; k++) {
        cumw += 0.001f + ew[k]*rw;             // MBW + scaled softmax
        cumh += 0.001f + eh[k]*rh;
        float cwn = (k == 7) ? 3.f : fmaf(6.f, cumw, -3.f);
        float chn = (k == 7) ? 3.f : fmaf(6.f, cumh, -3.f);
        float dn  = (k == 7) ? 1.f : (0.001f + sp[k]);   // d[k+1]; d[0]=d[8]=1
        if (xc >= cw) { icw = cw; iw = cwn - cw; ich = ch; ih = chn - ch; id0 = dprev; id1 = dn; }
        cw = cwn; ch = chn; dprev = dn;
    }

    float riw   = 1.f / iw;
    float delta = ih * riw;
    float theta = (xc - icw) * riw;
    float omt = 1.f - theta;
    float t1  = theta * omt;
    float th2 = theta * theta;
    float num = ih * (delta*th2 + id0*t1);
    float den = delta + (id0 + id1 - 2.f*delta)*t1;
    float y   = ich + num / den;
    float dnum = delta*delta*(id1*th2 + 2.f*delta*t1 + id0*omt*omt);
    float l = logf(dnum) - 2.f*logf(den);

    lad = inside ? l : 0.f;
    return inside ? y : xa;
}

// ---------------------------------------------------------------------------
// conv3 (64 -> 276, 3x3, pad 1) fused with RQS + output write + logdet partial.
// Block: 16x32 pixel tile, all 64 input ch staged (156KB) + per-c weights
// (55KB).  Thread: 2 adjacent pixels, 23 accumulators, 12 channel groups.
// ---------------------------------------------------------------------------
__global__ void __launch_bounds__(256, 1) k_conv3_rqs(const float* __restrict__ x,
                                                      const float* __restrict__ b3,
                                                      float* __restrict__ out) {
    extern __shared__ float sm[];
    float* sIn = sm;            // 64 * 612
    float* sW  = sm + 39168;    // 576 * 24

    int b = blockIdx.y;
    int tile = blockIdx.x;
    int r0 = (tile >> 2) << 4;
    int c0 = (tile & 3) << 5;
    int t = threadIdx.x;

    for (int i = t; i < 64*612; i += 256) {
        int ch = i / 612; int rem = i - ch*612;
        int lr = rem / 34; int lc = rem - lr*34;
        int gr = r0 + lr - 1, gc = c0 + lc - 1;
        float v = 0.f;
        if ((unsigned)gr < 128u && (unsigned)gc < 128u)
            v = g_h2[(((size_t)(b*64 + ch)) << 14) + (gr << 7) + gc];
        sIn[i] = v;
    }

    int r = t >> 4, cx = (t & 15) << 1;
    int gr = r0 + r, gc = c0 + cx;
    int par0 = (gr + gc) & 1;    // 1 => frozen (mask=1) at first pixel
    float ladsum = 0.f;

    for (int c = 0; c < 12; c++) {
        __syncthreads();
        {
            const float4* src = (const float4*)&g_W3t[c*13824];
            float4* dst = (float4*)sW;
            for (int i = t; i < 3456; i += 256) dst[i] = src[i];
        }
        __syncthreads();

        float a0[23], a1[23];
        #pragma unroll
        for (int s = 0; s < 23; s++) { float bb = b3[c*23 + s]; a0[s] = bb; a1[s] = bb; }

        for (int ic = 0; ic < 64; ic++) {
            #pragma unroll
            for (int kh = 0; kh < 3; kh++) {
                const float* inr = &sIn[ic*612 + (r + kh)*34 + cx];
                #pragma unroll
                for (int kw = 0; kw < 3; kw++) {
                    float v0 = inr[kw];
                    float v1 = inr[kw + 1];
                    const float4* wr = (const float4*)&sW[((ic*3 + kh)*3 + kw)*24];
                    #pragma unroll
                    for (int q = 0; q < 6; q++) {
                        float4 w = wr[q];
                        int s4 = q*4;
                        a0[s4] = fmaf(w.x, v0, a0[s4]); a1[s4] = fmaf(w.x, v1, a1[s4]);
                        if (s4+1 < 23) { a0[s4+1] = fmaf(w.y, v0, a0[s4+1]); a1[s4+1] = fmaf(w.y, v1, a1[s4+1]); }
                        if (s4+2 < 23) { a0[s4+2] = fmaf(w.z, v0, a0[s4+2]); a1[s4+2] = fmaf(w.z, v1, a1[s4+2]); }
                        if (s4+3 < 23) { a0[s4+3] = fmaf(w.w, v0, a0[s4+3]); a1[s4+3] = fmaf(w.w, v1, a1[s4+3]); }
                    }
                }
            }
        }

        // RQS epilogue for this channel, both pixels
        size_t xbase = (((size_t)(b*12 + c)) << 14) + (gr << 7) + gc;
        float xv0 = x[xbase], xv1 = x[xbase + 1];
        float xa0 = par0 ? 0.f : xv0;   // active value (even parity)
        float xf0 = par0 ? xv0 : 0.f;   // frozen value (odd parity)
        float xa1 = par0 ? xv1 : 0.f;   // neighbor has opposite parity
        float xf1 = par0 ? 0.f : xv1;

        float lad0, lad1;
        float y0 = rqs_eval(a0, xa0, lad0);
        float y1 = rqs_eval(a1, xa1, lad1);
        out[xbase]     = xf0 + y0;
        out[xbase + 1] = xf1 + y1;
        ladsum += lad0 + lad1;
    }

    // deterministic block reduction of logdet partials (reuse smem)
    __syncthreads();
    sm[t] = ladsum;
    __syncthreads();
    for (int off = 128; off > 0; off >>= 1) {
        if (t < off) sm[t] += sm[t + off];
        __syncthreads();
    }
    if (t == 0) g_lad[b*32 + tile] = sm[0];
}

// ---------------------------------------------------------------------------
// Final logdet reduction: 32 tile-partials per image + input logdet.
// ---------------------------------------------------------------------------
__global__ void k_red(const float* __restrict__ logdet_in, float* __restrict__ out) {
    int b = blockIdx.x, lane = threadIdx.x;
    float v = g_lad[b*32 + lane];
    #pragma unroll
    for (int o = 16; o > 0; o >>= 1) v += __shfl_down_sync(0xffffffffu, v, o);
    if (lane == 0) out[XOUT_SIZE + b] = logdet_in[b] + v;
}

// ---------------------------------------------------------------------------
extern "C" void kernel_launch(void* const* d_in, const int* in_sizes, int n_in,
                              void* d_out, int out_size) {
    const float* x      = (const float*)d_in[0];
    const float* logdet = (const float*)d_in[1];
    const float* cond   = (const float*)d_in[2];
    const float* W1     = (const float*)d_in[3];
    const float* b1     = (const float*)d_in[4];
    const float* W2     = (const float*)d_in[5];
    const float* b2     = (const float*)d_in[6];
    const float* W3     = (const float*)d_in[7];
    const float* b3     = (const float*)d_in[8];
    float* out = (float*)d_out;

    const int smem1 = (9792 + 9216) * 4;      // 76,032 B
    const int smem3 = (39168 + 13824) * 4;    // 211,968 B
    cudaFuncSetAttribute(k_conv1, cudaFuncAttributeMaxDynamicSharedMemorySize, smem1);
    cudaFuncSetAttribute(k_conv3_rqs, cudaFuncAttributeMaxDynamicSharedMemorySize, smem3);

    k_trans<<<700, 256>>>(W1, W2, W3);
    k_conv1<<<dim3(32, 16), 256, smem1>>>(x, cond, b1);
    k_conv2<<<1024, 256>>>(b2);
    k_conv3_rqs<<<dim3(32, 16), 256, smem3>>>(x, b3, out);
    k_red<<<16, 32>>>(logdet, out);
}